// round 6
// baseline (speedup 1.0000x reference)
#include <cuda_runtime.h>
#include <cuda_bf16.h>
#include <cstdint>
#include <math.h>

#define NN 100000
#define DD 128
#define EE 250000
#define TT 3
#define ND (NN*DD)

// -------- scratch --------
__device__ float g_feat[ND];
__device__ float g_t1[ND];
__device__ float g_t2[ND];
__device__ float g_key[3*ND];
__device__ float g_ska[3*ND];
__device__ float g_v[3*ND];
__device__ int   g_cnt[TT*NN];
__device__ float g_inv[TT*NN];
__device__ float g_gscale[NN];
__device__ float g_colsum[DD];
__device__ float g_colsq[DD];
__device__ float g_wqa[DD*DD];
__device__ float g_wka[DD*DD];

// -------- small kernels --------

__global__ void gather_feat_k(const float* __restrict__ n_emb, const int* __restrict__ ind,
                              float* __restrict__ feat) {
    int idx = blockIdx.x * blockDim.x + threadIdx.x;
    if (idx >= ND) return;
    int n = idx >> 7;
    feat[idx] = n_emb[(long)ind[n] * DD + (idx & 127)];
}

__global__ void count_k(const int* __restrict__ dst, int* __restrict__ cnt) {
    int e = blockIdx.x * blockDim.x + threadIdx.x;
    if (e >= TT*EE) return;
    int t = e / EE;
    atomicAdd(&cnt[t * NN + dst[e]], 1);
}

__global__ void prep_k(const int* __restrict__ cnt, float* __restrict__ inv,
                       float* __restrict__ gscale) {
    int n = blockIdx.x * blockDim.x + threadIdx.x;
    if (n >= NN) return;
    int c0 = cnt[n], c1 = cnt[NN + n], c2 = cnt[2*NN + n];
    inv[n]        = 1.f / (float)max(c0, 1);
    inv[NN + n]   = 1.f / (float)max(c1, 1);
    inv[2*NN + n] = 1.f / (float)max(c2, 1);
    gscale[n] = (float)((c0 > 0) + (c1 > 0) + (c2 > 0));
}

__device__ __forceinline__ void red_add_v4(float* p, float4 v) {
    asm volatile("red.global.add.v4.f32 [%0], {%1,%2,%3,%4};"
                 :: "l"(p), "f"(v.x), "f"(v.y), "f"(v.z), "f"(v.w) : "memory");
}

__global__ void gcn_edge_k(const float* __restrict__ feat, const float* __restrict__ emb,
                           const int* __restrict__ src, const int* __restrict__ dst,
                           const float* __restrict__ inv, float* __restrict__ acc) {
    int gw = (blockIdx.x * blockDim.x + threadIdx.x) >> 5;
    int lane = threadIdx.x & 31;
    if (gw >= TT*EE) return;
    int t = gw / EE;
    int s = src[gw], d = dst[gw];
    float w = inv[t * NN + d];
    float4 f = reinterpret_cast<const float4*>(feat + (long)s * DD)[lane];
    float4 e = reinterpret_cast<const float4*>(emb + t * DD)[lane];
    float4 v = make_float4(-f.x*e.x*w, -f.y*e.y*w, -f.z*e.z*w, -f.w*e.w*w);
    red_add_v4(acc + (long)d * DD + lane*4, v);
}

__global__ void attn_edge_k(const float* __restrict__ feat, const float* __restrict__ emb,
                            const int* __restrict__ src, const int* __restrict__ dst,
                            const float* __restrict__ inv, float* __restrict__ key) {
    int gw = (blockIdx.x * blockDim.x + threadIdx.x) >> 5;
    int lane = threadIdx.x & 31;
    if (gw >= TT*EE) return;
    int t = gw / EE;
    int s = src[gw], d = dst[gw];
    float w = inv[t * NN + d];
    float4 f = reinterpret_cast<const float4*>(feat + (long)s * DD)[lane];
    float4 e = reinterpret_cast<const float4*>(emb + t * DD)[lane];
    float4 v = make_float4(f.x*e.x*w, f.y*e.y*w, f.z*e.z*w, f.w*e.w*w);
    red_add_v4(key + (long)t * ND + (long)d * DD + lane*4, v);
}

// -------- tf32 tensor-core GEMM --------
// ASRC: 0 = A plain; 1 = BN(apply)+ReLU on A; 2 = softmax-combine(qa=A, ska=x1, vv=x2);
//       3 = A(t1 edge sums) + x1(feat)*x2(gscale)
// EPI:  0 = store; 1 = C += acc + bias; 2 = store + column sum/sumsq atomics

__device__ __forceinline__ uint32_t f2tf32(float f) {
    uint32_t o;
    asm("cvt.rna.tf32.f32 %0, %1;" : "=r"(o) : "f"(f));
    return o;
}

__device__ __forceinline__ void mma_tf32(float* c, const uint32_t* a, const uint32_t* b) {
    asm volatile("mma.sync.aligned.m16n8k8.row.col.f32.tf32.tf32.f32 "
                 "{%0,%1,%2,%3}, {%4,%5,%6,%7}, {%8,%9}, {%0,%1,%2,%3};"
                 : "+f"(c[0]), "+f"(c[1]), "+f"(c[2]), "+f"(c[3])
                 : "r"(a[0]), "r"(a[1]), "r"(a[2]), "r"(a[3]), "r"(b[0]), "r"(b[1]));
}

template<int ASRC, int EPI>
__global__ __launch_bounds__(256) void gemm_tc(
    const float* __restrict__ A, const float* __restrict__ B,
    float* __restrict__ C, const float* __restrict__ bias, int M,
    const float* __restrict__ gamma, const float* __restrict__ beta,
    float* __restrict__ colsum, float* __restrict__ colsq,
    const float* __restrict__ x1, const float* __restrict__ x2) {
    __shared__ uint32_t As[128][36];
    __shared__ uint32_t Bs[32][136];
    __shared__ float sm_mean[128], sm_scale[128], sm_beta[128];
    __shared__ float s_sum[128], s_sq[128];
    int tid = threadIdx.x;
    int lane = tid & 31, wid = tid >> 5;
    int wm = wid & 3, wn = wid >> 2;
    int g = lane >> 2, q = lane & 3;
    long m0 = (long)blockIdx.x * 128;

    if (ASRC == 1 && tid < 128) {
        const float invN = 1.f / (float)NN;
        float mean = colsum[tid] * invN;
        float var  = colsq[tid] * invN - mean * mean;
        float rstd = rsqrtf(var + 1e-5f);
        sm_mean[tid] = mean;
        sm_scale[tid] = rstd * gamma[tid];
        sm_beta[tid] = beta[tid];
    }
    if (EPI == 2 && tid < 128) { s_sum[tid] = 0.f; s_sq[tid] = 0.f; }
    if (ASRC == 1) __syncthreads();

    float acc[2][8][4];
    #pragma unroll
    for (int mt = 0; mt < 2; mt++)
        #pragma unroll
        for (int nt = 0; nt < 8; nt++)
            #pragma unroll
            for (int i = 0; i < 4; i++) acc[mt][nt][i] = 0.f;

    for (int k0 = 0; k0 < 128; k0 += 32) {
        #pragma unroll
        for (int i = 0; i < 4; i++) {
            int idx4 = (tid + 256 * i) * 4;
            int r = idx4 >> 5, c = idx4 & 31;
            long row = m0 + r;
            float4 v = make_float4(0.f, 0.f, 0.f, 0.f);
            if (row < M) {
                long base = row * 128 + k0 + c;
                if (ASRC == 0) {
                    v = *reinterpret_cast<const float4*>(A + base);
                } else if (ASRC == 1) {
                    v = *reinterpret_cast<const float4*>(A + base);
                    int cc = k0 + c;
                    float* pv = &v.x;
                    #pragma unroll
                    for (int j = 0; j < 4; j++) {
                        float x = (pv[j] - sm_mean[cc+j]) * sm_scale[cc+j] + sm_beta[cc+j];
                        pv[j] = x > 0.f ? x : 0.f;
                    }
                } else if (ASRC == 3) {
                    v = *reinterpret_cast<const float4*>(A + base);
                    float4 f = *reinterpret_cast<const float4*>(x1 + base);
                    float s = x2[row];
                    v.x += f.x * s; v.y += f.y * s; v.z += f.z * s; v.w += f.w * s;
                } else { // ASRC == 2: softmax combine
                    float4 qv = *reinterpret_cast<const float4*>(A + base);
                    float4 s0 = *reinterpret_cast<const float4*>(x1 + base);
                    float4 s1 = *reinterpret_cast<const float4*>(x1 + base + (long)ND);
                    float4 s2 = *reinterpret_cast<const float4*>(x1 + base + 2L*ND);
                    float4 v0 = *reinterpret_cast<const float4*>(x2 + base);
                    float4 v1 = *reinterpret_cast<const float4*>(x2 + base + (long)ND);
                    float4 v2 = *reinterpret_cast<const float4*>(x2 + base + 2L*ND);
                    const float* pq = &qv.x; const float* p0 = &s0.x; const float* p1 = &s1.x;
                    const float* p2 = &s2.x; const float* w0 = &v0.x; const float* w1 = &v1.x;
                    const float* w2 = &v2.x; float* pv = &v.x;
                    #pragma unroll
                    for (int j = 0; j < 4; j++) {
                        float l0 = pq[j] - p0[j], l1 = pq[j] - p1[j], l2 = pq[j] - p2[j];
                        float mx = fmaxf(l0, fmaxf(l1, l2));
                        float e0 = __expf(l0 - mx), e1 = __expf(l1 - mx), e2 = __expf(l2 - mx);
                        pv[j] = (e0 * w0[j] + e1 * w1[j] + e2 * w2[j]) / (e0 + e1 + e2);
                    }
                }
            }
            uint4 t = make_uint4(f2tf32(v.x), f2tf32(v.y), f2tf32(v.z), f2tf32(v.w));
            *reinterpret_cast<uint4*>(&As[r][c]) = t;
        }
        #pragma unroll
        for (int i = 0; i < 4; i++) {
            int idx4 = (tid + 256 * i) * 4;
            int r = idx4 >> 7, c = idx4 & 127;
            float4 v = *reinterpret_cast<const float4*>(B + (k0 + r) * 128 + c);
            uint4 t = make_uint4(f2tf32(v.x), f2tf32(v.y), f2tf32(v.z), f2tf32(v.w));
            *reinterpret_cast<uint4*>(&Bs[r][c]) = t;
        }
        __syncthreads();

        #pragma unroll
        for (int ks = 0; ks < 4; ks++) {
            int kc = ks * 8;
            uint32_t a[2][4], b[8][2];
            #pragma unroll
            for (int mt = 0; mt < 2; mt++) {
                int row = wm * 32 + mt * 16 + g;
                a[mt][0] = As[row][kc + q];
                a[mt][1] = As[row + 8][kc + q];
                a[mt][2] = As[row][kc + q + 4];
                a[mt][3] = As[row + 8][kc + q + 4];
            }
            #pragma unroll
            for (int nt = 0; nt < 8; nt++) {
                int col = wn * 64 + nt * 8 + g;
                b[nt][0] = Bs[kc + q][col];
                b[nt][1] = Bs[kc + q + 4][col];
            }
            #pragma unroll
            for (int mt = 0; mt < 2; mt++)
                #pragma unroll
                for (int nt = 0; nt < 8; nt++)
                    mma_tf32(acc[mt][nt], a[mt], b[nt]);
        }
        __syncthreads();
    }

    #pragma unroll
    for (int mt = 0; mt < 2; mt++) {
        #pragma unroll
        for (int h = 0; h < 2; h++) {
            long row = m0 + wm * 32 + mt * 16 + g + h * 8;
            if (row >= M) continue;
            #pragma unroll
            for (int nt = 0; nt < 8; nt++) {
                int col = wn * 64 + nt * 8 + q * 2;
                float2* cp = reinterpret_cast<float2*>(&C[row * 128 + col]);
                float v0 = acc[mt][nt][h * 2], v1 = acc[mt][nt][h * 2 + 1];
                if (EPI == 1) {
                    float2 prev = *cp;
                    *cp = make_float2(prev.x + v0 + bias[col], prev.y + v1 + bias[col + 1]);
                } else {
                    *cp = make_float2(v0, v1);
                    if (EPI == 2) {
                        atomicAdd(&s_sum[col], v0);   atomicAdd(&s_sq[col], v0 * v0);
                        atomicAdd(&s_sum[col+1], v1); atomicAdd(&s_sq[col+1], v1 * v1);
                    }
                }
            }
        }
    }
    if (EPI == 2) {
        __syncthreads();
        if (tid < 128) {
            atomicAdd(&colsum[tid], s_sum[tid]);
            atomicAdd(&colsq[tid], s_sq[tid]);
        }
    }
}

// Dual-B GEMM: C1 = A@B1, C2 = A@B2 — A (key) staged once. Dynamic smem (53.2KB).
#define DUAL_SMEM_BYTES ((128*36 + 2*32*136) * 4)

__global__ __launch_bounds__(256) void gemm_dual(
    const float* __restrict__ A, const float* __restrict__ B1, const float* __restrict__ B2,
    float* __restrict__ C1, float* __restrict__ C2, int M) {
    extern __shared__ uint32_t dyn_smem[];
    uint32_t (*As)[36]   = reinterpret_cast<uint32_t(*)[36]>(dyn_smem);
    uint32_t (*Bs1)[136] = reinterpret_cast<uint32_t(*)[136]>(dyn_smem + 128*36);
    uint32_t (*Bs2)[136] = reinterpret_cast<uint32_t(*)[136]>(dyn_smem + 128*36 + 32*136);
    int tid = threadIdx.x;
    int lane = tid & 31, wid = tid >> 5;
    int wm = wid & 3, wn = wid >> 2;
    int g = lane >> 2, q = lane & 3;
    long m0 = (long)blockIdx.x * 128;

    float ac1[2][8][4], ac2[2][8][4];
    #pragma unroll
    for (int mt = 0; mt < 2; mt++)
        #pragma unroll
        for (int nt = 0; nt < 8; nt++)
            #pragma unroll
            for (int i = 0; i < 4; i++) { ac1[mt][nt][i] = 0.f; ac2[mt][nt][i] = 0.f; }

    for (int k0 = 0; k0 < 128; k0 += 32) {
        #pragma unroll
        for (int i = 0; i < 4; i++) {
            int idx4 = (tid + 256 * i) * 4;
            int r = idx4 >> 5, c = idx4 & 31;
            long row = m0 + r;
            float4 v = make_float4(0.f, 0.f, 0.f, 0.f);
            if (row < M) v = *reinterpret_cast<const float4*>(A + row * 128 + k0 + c);
            uint4 t = make_uint4(f2tf32(v.x), f2tf32(v.y), f2tf32(v.z), f2tf32(v.w));
            *reinterpret_cast<uint4*>(&As[r][c]) = t;
        }
        #pragma unroll
        for (int i = 0; i < 4; i++) {
            int idx4 = (tid + 256 * i) * 4;
            int r = idx4 >> 7, c = idx4 & 127;
            float4 v1 = *reinterpret_cast<const float4*>(B1 + (k0 + r) * 128 + c);
            float4 v2 = *reinterpret_cast<const float4*>(B2 + (k0 + r) * 128 + c);
            *reinterpret_cast<uint4*>(&Bs1[r][c]) =
                make_uint4(f2tf32(v1.x), f2tf32(v1.y), f2tf32(v1.z), f2tf32(v1.w));
            *reinterpret_cast<uint4*>(&Bs2[r][c]) =
                make_uint4(f2tf32(v2.x), f2tf32(v2.y), f2tf32(v2.z), f2tf32(v2.w));
        }
        __syncthreads();

        #pragma unroll
        for (int ks = 0; ks < 4; ks++) {
            int kc = ks * 8;
            uint32_t a[2][4], b1[8][2], b2[8][2];
            #pragma unroll
            for (int mt = 0; mt < 2; mt++) {
                int row = wm * 32 + mt * 16 + g;
                a[mt][0] = As[row][kc + q];
                a[mt][1] = As[row + 8][kc + q];
                a[mt][2] = As[row][kc + q + 4];
                a[mt][3] = As[row + 8][kc + q + 4];
            }
            #pragma unroll
            for (int nt = 0; nt < 8; nt++) {
                int col = wn * 64 + nt * 8 + g;
                b1[nt][0] = Bs1[kc + q][col];      b1[nt][1] = Bs1[kc + q + 4][col];
                b2[nt][0] = Bs2[kc + q][col];      b2[nt][1] = Bs2[kc + q + 4][col];
            }
            #pragma unroll
            for (int mt = 0; mt < 2; mt++)
                #pragma unroll
                for (int nt = 0; nt < 8; nt++) {
                    mma_tf32(ac1[mt][nt], a[mt], b1[nt]);
                    mma_tf32(ac2[mt][nt], a[mt], b2[nt]);
                }
        }
        __syncthreads();
    }

    #pragma unroll
    for (int mt = 0; mt < 2; mt++) {
        #pragma unroll
        for (int h = 0; h < 2; h++) {
            long row = m0 + wm * 32 + mt * 16 + g + h * 8;
            if (row >= M) continue;
            #pragma unroll
            for (int nt = 0; nt < 8; nt++) {
                int col = wn * 64 + nt * 8 + q * 2;
                *reinterpret_cast<float2*>(&C1[row * 128 + col]) =
                    make_float2(ac1[mt][nt][h*2], ac1[mt][nt][h*2+1]);
                *reinterpret_cast<float2*>(&C2[row * 128 + col]) =
                    make_float2(ac2[mt][nt][h*2], ac2[mt][nt][h*2+1]);
            }
        }
    }
}

// -------- host --------

extern "C" void kernel_launch(void* const* d_in, const int* in_sizes, int n_in,
                              void* d_out, int out_size) {
    const float* e_emb = (const float*)d_in[1];
    const int* node_ind = (const int*)d_in[26];
    const int* edge_src = (const int*)d_in[27];
    const int* edge_dst = (const int*)d_in[28];

    float *feat, *t1, *t2, *key, *ska, *vv, *inv, *gscale, *colsum, *colsq, *wqa, *wka;
    int* cnt;
    cudaGetSymbolAddress((void**)&feat, g_feat);
    cudaGetSymbolAddress((void**)&t1, g_t1);
    cudaGetSymbolAddress((void**)&t2, g_t2);
    cudaGetSymbolAddress((void**)&key, g_key);
    cudaGetSymbolAddress((void**)&ska, g_ska);
    cudaGetSymbolAddress((void**)&vv, g_v);
    cudaGetSymbolAddress((void**)&cnt, g_cnt);
    cudaGetSymbolAddress((void**)&inv, g_inv);
    cudaGetSymbolAddress((void**)&gscale, g_gscale);
    cudaGetSymbolAddress((void**)&colsum, g_colsum);
    cudaGetSymbolAddress((void**)&colsq, g_colsq);
    cudaGetSymbolAddress((void**)&wqa, g_wqa);
    cudaGetSymbolAddress((void**)&wka, g_wka);

    cudaFuncSetAttribute(gemm_dual, cudaFuncAttributeMaxDynamicSharedMemorySize,
                         DUAL_SMEM_BYTES);

    const int TPB = 256;
    const int ND_BLK = (ND + TPB - 1) / TPB;
    const int EDGE_BLK = (TT*EE*32 + TPB - 1) / TPB;
    const int G1 = (NN + 127) / 128;
    const int G3 = (TT*NN + 127) / 128;

    cudaMemsetAsync(cnt, 0, TT*NN*sizeof(int), 0);
    count_k<<<(TT*EE + TPB - 1)/TPB, TPB>>>(edge_dst, cnt);
    prep_k<<<(NN + TPB - 1)/TPB, TPB>>>(cnt, inv, gscale);
    gather_feat_k<<<ND_BLK, TPB>>>((const float*)d_in[0], node_ind, feat);

    const float* gcn_w1[2]    = {(const float*)d_in[2],  (const float*)d_in[14]};
    const float* gcn_gamma[2] = {(const float*)d_in[3],  (const float*)d_in[15]};
    const float* gcn_beta[2]  = {(const float*)d_in[4],  (const float*)d_in[16]};
    const float* gcn_w2[2]    = {(const float*)d_in[5],  (const float*)d_in[17]};
    const float* gcn_b2[2]    = {(const float*)d_in[6],  (const float*)d_in[18]};
    const float* at_wq[2]     = {(const float*)d_in[7],  (const float*)d_in[19]};
    const float* at_wk[2]     = {(const float*)d_in[8],  (const float*)d_in[20]};
    const float* at_wv[2]     = {(const float*)d_in[9],  (const float*)d_in[21]};
    const float* at_wa[2]     = {(const float*)d_in[10], (const float*)d_in[22]};
    const float* at_wp[2]     = {(const float*)d_in[12], (const float*)d_in[24]};
    const float* at_bp[2]     = {(const float*)d_in[13], (const float*)d_in[25]};

    for (int L = 0; L < 2; L++) {
        // ---- GCN layer ----
        cudaMemsetAsync(t1, 0, (size_t)ND*sizeof(float), 0);
        cudaMemsetAsync(colsum, 0, DD*sizeof(float), 0);
        cudaMemsetAsync(colsq, 0, DD*sizeof(float), 0);
        gcn_edge_k<<<EDGE_BLK, TPB>>>(feat, e_emb, edge_src, edge_dst, inv, t1);
        // t2 = (feat*gscale + t1) @ w1 ; column stats accumulated in epilogue
        gemm_tc<3,2><<<G1, 256>>>(t1, gcn_w1[L], t2, nullptr, NN,
                                  nullptr, nullptr, colsum, colsq, feat, gscale);
        // feat += relu(BN(t2)) @ w2 + b2 ; BN applied in A-stage
        gemm_tc<1,1><<<G1, 256>>>(t2, gcn_w2[L], feat, gcn_b2[L], NN,
                                  gcn_gamma[L], gcn_beta[L], colsum, colsq, nullptr, nullptr);

        // ---- Attention layer ----
        gemm_tc<0,0><<<1, 256>>>(at_wq[L], at_wa[L], wqa, nullptr, 128,
                                 nullptr, nullptr, nullptr, nullptr, nullptr, nullptr);
        gemm_tc<0,0><<<1, 256>>>(at_wk[L], at_wa[L], wka, nullptr, 128,
                                 nullptr, nullptr, nullptr, nullptr, nullptr, nullptr);
        cudaMemsetAsync(key, 0, (size_t)3*ND*sizeof(float), 0);
        attn_edge_k<<<EDGE_BLK, TPB>>>(feat, e_emb, edge_src, edge_dst, inv, key);
        gemm_tc<0,0><<<G1, 256>>>(feat, wqa, t1, nullptr, NN,
                                  nullptr, nullptr, nullptr, nullptr, nullptr, nullptr); // qa
        gemm_dual<<<G3, 256, DUAL_SMEM_BYTES>>>(key, wka, at_wv[L], ska, vv, TT*NN);
        // feat += softmax-combine(qa, ska, vv) @ wp + bp ; combine in A-stage
        gemm_tc<2,1><<<G1, 256>>>(t1, at_wp[L], feat, at_bp[L], NN,
                                  nullptr, nullptr, nullptr, nullptr, ska, vv);
    }

    cudaMemcpyAsync(d_out, feat, (size_t)ND*sizeof(float), cudaMemcpyDeviceToDevice, 0);
    if (out_size >= ND + TT*DD) {
        cudaMemcpyAsync((float*)d_out + ND, e_emb, TT*DD*sizeof(float),
                        cudaMemcpyDeviceToDevice, 0);
    }
}

// round 7
// speedup vs baseline: 1.2952x; 1.2952x over previous
#include <cuda_runtime.h>
#include <cuda_bf16.h>
#include <cstdint>
#include <math.h>

#define NN 100000
#define DD 128
#define EE 250000
#define TT 3
#define ND (NN*DD)

// -------- scratch --------
__device__ float g_feat[ND];
__device__ float g_t1[ND];
__device__ float g_t2[ND];
__device__ float g_key[3*ND];
__device__ float g_ska[3*ND];
__device__ float g_v[3*ND];
__device__ int   g_cnt[TT*NN];
__device__ float g_inv[TT*NN];
__device__ float g_gscale[NN];
__device__ float g_colsum[DD];
__device__ float g_colsq[DD];
__device__ float g_wqa[DD*DD];
__device__ float g_wka[DD*DD];

// -------- small kernels (float4-vectorized) --------

#define ND4 (ND/4)

__global__ void gather_feat_k(const float* __restrict__ n_emb, const int* __restrict__ ind,
                              float* __restrict__ feat) {
    int idx = blockIdx.x * blockDim.x + threadIdx.x;
    if (idx >= ND4) return;
    int n = idx >> 5;   // 32 float4 per node
    reinterpret_cast<float4*>(feat)[idx] =
        reinterpret_cast<const float4*>(n_emb)[(long)ind[n] * 32 + (idx & 31)];
}

__global__ void count_k(const int* __restrict__ dst, int* __restrict__ cnt) {
    int e = blockIdx.x * blockDim.x + threadIdx.x;
    if (e >= TT*EE) return;
    int t = e / EE;
    atomicAdd(&cnt[t * NN + dst[e]], 1);
}

__global__ void prep_k(const int* __restrict__ cnt, float* __restrict__ inv,
                       float* __restrict__ gscale) {
    int n = blockIdx.x * blockDim.x + threadIdx.x;
    if (n >= NN) return;
    int c0 = cnt[n], c1 = cnt[NN + n], c2 = cnt[2*NN + n];
    inv[n]        = 1.f / (float)max(c0, 1);
    inv[NN + n]   = 1.f / (float)max(c1, 1);
    inv[2*NN + n] = 1.f / (float)max(c2, 1);
    gscale[n] = (float)((c0 > 0) + (c1 > 0) + (c2 > 0));
}

__global__ void init_acc_k(const float* __restrict__ feat, const float* __restrict__ gscale,
                           float* __restrict__ acc) {
    int idx = blockIdx.x * blockDim.x + threadIdx.x;
    if (idx >= ND4) return;
    float s = gscale[idx >> 5];
    float4 f = reinterpret_cast<const float4*>(feat)[idx];
    reinterpret_cast<float4*>(acc)[idx] = make_float4(f.x*s, f.y*s, f.z*s, f.w*s);
}

__device__ __forceinline__ void red_add_v4(float* p, float4 v) {
    asm volatile("red.global.add.v4.f32 [%0], {%1,%2,%3,%4};"
                 :: "l"(p), "f"(v.x), "f"(v.y), "f"(v.z), "f"(v.w) : "memory");
}

__global__ void gcn_edge_k(const float* __restrict__ feat, const float* __restrict__ emb,
                           const int* __restrict__ src, const int* __restrict__ dst,
                           const float* __restrict__ inv, float* __restrict__ acc) {
    int gw = (blockIdx.x * blockDim.x + threadIdx.x) >> 5;
    int lane = threadIdx.x & 31;
    if (gw >= TT*EE) return;
    int t = gw / EE;
    int s = src[gw], d = dst[gw];
    float w = inv[t * NN + d];
    float4 f = reinterpret_cast<const float4*>(feat + (long)s * DD)[lane];
    float4 e = reinterpret_cast<const float4*>(emb + t * DD)[lane];
    float4 v = make_float4(-f.x*e.x*w, -f.y*e.y*w, -f.z*e.z*w, -f.w*e.w*w);
    red_add_v4(acc + (long)d * DD + lane*4, v);
}

__global__ void attn_edge_k(const float* __restrict__ feat, const float* __restrict__ emb,
                            const int* __restrict__ src, const int* __restrict__ dst,
                            const float* __restrict__ inv, float* __restrict__ key) {
    int gw = (blockIdx.x * blockDim.x + threadIdx.x) >> 5;
    int lane = threadIdx.x & 31;
    if (gw >= TT*EE) return;
    int t = gw / EE;
    int s = src[gw], d = dst[gw];
    float w = inv[t * NN + d];
    float4 f = reinterpret_cast<const float4*>(feat + (long)s * DD)[lane];
    float4 e = reinterpret_cast<const float4*>(emb + t * DD)[lane];
    float4 v = make_float4(f.x*e.x*w, f.y*e.y*w, f.z*e.z*w, f.w*e.w*w);
    red_add_v4(key + (long)t * ND + (long)d * DD + lane*4, v);
}

// -------- tf32 tensor-core GEMM: C[M,128] = A[M,128] @ B[128,128] --------
// EPI==1: C += acc + bias[col]

__device__ __forceinline__ uint32_t f2tf32(float f) {
    uint32_t o;
    asm("cvt.rna.tf32.f32 %0, %1;" : "=r"(o) : "f"(f));
    return o;
}

__device__ __forceinline__ void mma_tf32(float* c, const uint32_t* a, const uint32_t* b) {
    asm volatile("mma.sync.aligned.m16n8k8.row.col.f32.tf32.tf32.f32 "
                 "{%0,%1,%2,%3}, {%4,%5,%6,%7}, {%8,%9}, {%0,%1,%2,%3};"
                 : "+f"(c[0]), "+f"(c[1]), "+f"(c[2]), "+f"(c[3])
                 : "r"(a[0]), "r"(a[1]), "r"(a[2]), "r"(a[3]), "r"(b[0]), "r"(b[1]));
}

template<int EPI>
__global__ __launch_bounds__(256) void gemm_tc(const float* __restrict__ A,
                                               const float* __restrict__ B,
                                               float* __restrict__ C,
                                               const float* __restrict__ bias, int M) {
    __shared__ uint32_t As[128][36];
    __shared__ uint32_t Bs[32][136];
    int tid = threadIdx.x;
    int lane = tid & 31, wid = tid >> 5;
    int wm = wid & 3, wn = wid >> 2;
    int g = lane >> 2, q = lane & 3;
    long m0 = (long)blockIdx.x * 128;

    float acc[2][8][4];
    #pragma unroll
    for (int mt = 0; mt < 2; mt++)
        #pragma unroll
        for (int nt = 0; nt < 8; nt++)
            #pragma unroll
            for (int i = 0; i < 4; i++) acc[mt][nt][i] = 0.f;

    for (int k0 = 0; k0 < 128; k0 += 32) {
        #pragma unroll
        for (int i = 0; i < 4; i++) {
            int idx = (tid + 256 * i) * 4;
            int r = idx >> 5, c = idx & 31;
            float4 v = make_float4(0.f, 0.f, 0.f, 0.f);
            if (m0 + r < M) v = *reinterpret_cast<const float4*>(A + (m0 + r) * 128 + k0 + c);
            uint4 t = make_uint4(f2tf32(v.x), f2tf32(v.y), f2tf32(v.z), f2tf32(v.w));
            *reinterpret_cast<uint4*>(&As[r][c]) = t;
        }
        #pragma unroll
        for (int i = 0; i < 4; i++) {
            int idx = (tid + 256 * i) * 4;
            int r = idx >> 7, c = idx & 127;
            float4 v = *reinterpret_cast<const float4*>(B + (k0 + r) * 128 + c);
            uint4 t = make_uint4(f2tf32(v.x), f2tf32(v.y), f2tf32(v.z), f2tf32(v.w));
            *reinterpret_cast<uint4*>(&Bs[r][c]) = t;
        }
        __syncthreads();

        #pragma unroll
        for (int ks = 0; ks < 4; ks++) {
            int kc = ks * 8;
            uint32_t a[2][4], b[8][2];
            #pragma unroll
            for (int mt = 0; mt < 2; mt++) {
                int row = wm * 32 + mt * 16 + g;
                a[mt][0] = As[row][kc + q];
                a[mt][1] = As[row + 8][kc + q];
                a[mt][2] = As[row][kc + q + 4];
                a[mt][3] = As[row + 8][kc + q + 4];
            }
            #pragma unroll
            for (int nt = 0; nt < 8; nt++) {
                int col = wn * 64 + nt * 8 + g;
                b[nt][0] = Bs[kc + q][col];
                b[nt][1] = Bs[kc + q + 4][col];
            }
            #pragma unroll
            for (int mt = 0; mt < 2; mt++)
                #pragma unroll
                for (int nt = 0; nt < 8; nt++)
                    mma_tf32(acc[mt][nt], a[mt], b[nt]);
        }
        __syncthreads();
    }

    #pragma unroll
    for (int mt = 0; mt < 2; mt++) {
        #pragma unroll
        for (int h = 0; h < 2; h++) {
            long row = m0 + wm * 32 + mt * 16 + g + h * 8;
            if (row >= M) continue;
            #pragma unroll
            for (int nt = 0; nt < 8; nt++) {
                int col = wn * 64 + nt * 8 + q * 2;
                float2* cp = reinterpret_cast<float2*>(&C[row * 128 + col]);
                float v0 = acc[mt][nt][h * 2], v1 = acc[mt][nt][h * 2 + 1];
                if (EPI == 0) {
                    *cp = make_float2(v0, v1);
                } else {
                    float2 prev = *cp;
                    *cp = make_float2(prev.x + v0 + bias[col], prev.y + v1 + bias[col + 1]);
                }
            }
        }
    }
}

// -------- BN / softmax kernels --------

__global__ void bn_stats_k(const float* __restrict__ h, float* __restrict__ colsum,
                           float* __restrict__ colsq) {
    __shared__ float ssum[128], ssq[128];
    int tid = threadIdx.x;
    if (tid < 128) { ssum[tid] = 0.f; ssq[tid] = 0.f; }
    __syncthreads();
    int c4 = tid & 31;          // float4 column
    int rstep = gridDim.x * 8;  // 256 threads = 8 rows per iter
    float4 s = make_float4(0,0,0,0), s2 = make_float4(0,0,0,0);
    for (int r = blockIdx.x * 8 + (tid >> 5); r < NN; r += rstep) {
        float4 x = reinterpret_cast<const float4*>(h)[(long)r * 32 + c4];
        s.x += x.x; s.y += x.y; s.z += x.z; s.w += x.w;
        s2.x += x.x*x.x; s2.y += x.y*x.y; s2.z += x.z*x.z; s2.w += x.w*x.w;
    }
    atomicAdd(&ssum[c4*4+0], s.x);  atomicAdd(&ssq[c4*4+0], s2.x);
    atomicAdd(&ssum[c4*4+1], s.y);  atomicAdd(&ssq[c4*4+1], s2.y);
    atomicAdd(&ssum[c4*4+2], s.z);  atomicAdd(&ssq[c4*4+2], s2.z);
    atomicAdd(&ssum[c4*4+3], s.w);  atomicAdd(&ssq[c4*4+3], s2.w);
    __syncthreads();
    if (tid < 128) {
        atomicAdd(&colsum[tid], ssum[tid]);
        atomicAdd(&colsq[tid], ssq[tid]);
    }
}

__global__ void bn_apply_relu_k(float* __restrict__ h, const float* __restrict__ gamma,
                                const float* __restrict__ beta,
                                const float* __restrict__ colsum,
                                const float* __restrict__ colsq) {
    __shared__ float sm_mean[128], sm_scale[128], sm_beta[128];
    int tid = threadIdx.x;
    if (tid < 128) {
        const float invN = 1.f / (float)NN;
        float mean = colsum[tid] * invN;
        float var  = colsq[tid] * invN - mean * mean;
        sm_mean[tid] = mean;
        sm_scale[tid] = rsqrtf(var + 1e-5f) * gamma[tid];
        sm_beta[tid] = beta[tid];
    }
    __syncthreads();
    int idx = blockIdx.x * blockDim.x + tid;
    if (idx >= ND4) return;
    int c = (idx & 31) * 4;
    float4 x = reinterpret_cast<float4*>(h)[idx];
    float4 o;
    o.x = fmaxf((x.x - sm_mean[c+0]) * sm_scale[c+0] + sm_beta[c+0], 0.f);
    o.y = fmaxf((x.y - sm_mean[c+1]) * sm_scale[c+1] + sm_beta[c+1], 0.f);
    o.z = fmaxf((x.z - sm_mean[c+2]) * sm_scale[c+2] + sm_beta[c+2], 0.f);
    o.w = fmaxf((x.w - sm_mean[c+3]) * sm_scale[c+3] + sm_beta[c+3], 0.f);
    reinterpret_cast<float4*>(h)[idx] = o;
}

__global__ void attn_combine_k(const float* __restrict__ qa, const float* __restrict__ ska,
                               const float* __restrict__ vv, float* __restrict__ o) {
    int idx = blockIdx.x * blockDim.x + threadIdx.x;
    if (idx >= ND4) return;
    float4 q  = reinterpret_cast<const float4*>(qa)[idx];
    float4 s0 = reinterpret_cast<const float4*>(ska)[idx];
    float4 s1 = reinterpret_cast<const float4*>(ska)[idx + ND4];
    float4 s2 = reinterpret_cast<const float4*>(ska)[idx + 2*ND4];
    float4 v0 = reinterpret_cast<const float4*>(vv)[idx];
    float4 v1 = reinterpret_cast<const float4*>(vv)[idx + ND4];
    float4 v2 = reinterpret_cast<const float4*>(vv)[idx + 2*ND4];
    float4 r;
    const float* pq = &q.x; const float* p0 = &s0.x; const float* p1 = &s1.x;
    const float* p2 = &s2.x; const float* w0 = &v0.x; const float* w1 = &v1.x;
    const float* w2 = &v2.x; float* pr = &r.x;
    #pragma unroll
    for (int j = 0; j < 4; j++) {
        float l0 = pq[j] - p0[j], l1 = pq[j] - p1[j], l2 = pq[j] - p2[j];
        float m = fmaxf(l0, fmaxf(l1, l2));
        float e0 = __expf(l0 - m), e1 = __expf(l1 - m), e2 = __expf(l2 - m);
        pr[j] = (e0 * w0[j] + e1 * w1[j] + e2 * w2[j]) / (e0 + e1 + e2);
    }
    reinterpret_cast<float4*>(o)[idx] = r;
}

// -------- host --------

extern "C" void kernel_launch(void* const* d_in, const int* in_sizes, int n_in,
                              void* d_out, int out_size) {
    const float* e_emb = (const float*)d_in[1];
    const int* node_ind = (const int*)d_in[26];
    const int* edge_src = (const int*)d_in[27];
    const int* edge_dst = (const int*)d_in[28];

    float *feat, *t1, *t2, *key, *ska, *vv, *inv, *gscale, *colsum, *colsq, *wqa, *wka;
    int* cnt;
    cudaGetSymbolAddress((void**)&feat, g_feat);
    cudaGetSymbolAddress((void**)&t1, g_t1);
    cudaGetSymbolAddress((void**)&t2, g_t2);
    cudaGetSymbolAddress((void**)&key, g_key);
    cudaGetSymbolAddress((void**)&ska, g_ska);
    cudaGetSymbolAddress((void**)&vv, g_v);
    cudaGetSymbolAddress((void**)&cnt, g_cnt);
    cudaGetSymbolAddress((void**)&inv, g_inv);
    cudaGetSymbolAddress((void**)&gscale, g_gscale);
    cudaGetSymbolAddress((void**)&colsum, g_colsum);
    cudaGetSymbolAddress((void**)&colsq, g_colsq);
    cudaGetSymbolAddress((void**)&wqa, g_wqa);
    cudaGetSymbolAddress((void**)&wka, g_wka);

    const int TPB = 256;
    const int ND4_BLK = (ND4 + TPB - 1) / TPB;        // 12500
    const int EDGE_BLK = (TT*EE*32 + TPB - 1) / TPB;  // 93750
    const int G1 = (NN + 127) / 128;                  // 782
    const int G3 = (TT*NN + 127) / 128;               // 2344

    cudaMemsetAsync(cnt, 0, TT*NN*sizeof(int), 0);
    count_k<<<(TT*EE + TPB - 1)/TPB, TPB>>>(edge_dst, cnt);
    prep_k<<<(NN + TPB - 1)/TPB, TPB>>>(cnt, inv, gscale);
    gather_feat_k<<<ND4_BLK, TPB>>>((const float*)d_in[0], node_ind, feat);

    const float* gcn_w1[2]    = {(const float*)d_in[2],  (const float*)d_in[14]};
    const float* gcn_gamma[2] = {(const float*)d_in[3],  (const float*)d_in[15]};
    const float* gcn_beta[2]  = {(const float*)d_in[4],  (const float*)d_in[16]};
    const float* gcn_w2[2]    = {(const float*)d_in[5],  (const float*)d_in[17]};
    const float* gcn_b2[2]    = {(const float*)d_in[6],  (const float*)d_in[18]};
    const float* at_wq[2]     = {(const float*)d_in[7],  (const float*)d_in[19]};
    const float* at_wk[2]     = {(const float*)d_in[8],  (const float*)d_in[20]};
    const float* at_wv[2]     = {(const float*)d_in[9],  (const float*)d_in[21]};
    const float* at_wa[2]     = {(const float*)d_in[10], (const float*)d_in[22]};
    const float* at_wp[2]     = {(const float*)d_in[12], (const float*)d_in[24]};
    const float* at_bp[2]     = {(const float*)d_in[13], (const float*)d_in[25]};

    for (int L = 0; L < 2; L++) {
        // ---- GCN layer ----
        init_acc_k<<<ND4_BLK, TPB>>>(feat, gscale, t1);
        gcn_edge_k<<<EDGE_BLK, TPB>>>(feat, e_emb, edge_src, edge_dst, inv, t1);
        gemm_tc<0><<<G1, 256>>>(t1, gcn_w1[L], t2, nullptr, NN);
        cudaMemsetAsync(colsum, 0, DD*sizeof(float), 0);
        cudaMemsetAsync(colsq, 0, DD*sizeof(float), 0);
        bn_stats_k<<<1024, 256>>>(t2, colsum, colsq);
        bn_apply_relu_k<<<ND4_BLK, TPB>>>(t2, gcn_gamma[L], gcn_beta[L], colsum, colsq);
        gemm_tc<1><<<G1, 256>>>(t2, gcn_w2[L], feat, gcn_b2[L], NN);

        // ---- Attention layer ----
        gemm_tc<0><<<1, 256>>>(at_wq[L], at_wa[L], wqa, nullptr, 128);
        gemm_tc<0><<<1, 256>>>(at_wk[L], at_wa[L], wka, nullptr, 128);
        cudaMemsetAsync(key, 0, (size_t)3*ND*sizeof(float), 0);
        attn_edge_k<<<EDGE_BLK, TPB>>>(feat, e_emb, edge_src, edge_dst, inv, key);
        gemm_tc<0><<<G1, 256>>>(feat, wqa, t1, nullptr, NN);
        gemm_tc<0><<<G3, 256>>>(key, wka, ska, nullptr, TT*NN);
        gemm_tc<0><<<G3, 256>>>(key, at_wv[L], vv, nullptr, TT*NN);
        attn_combine_k<<<ND4_BLK, TPB>>>(t1, ska, vv, t2);
        gemm_tc<1><<<G1, 256>>>(t2, at_wp[L], feat, at_bp[L], NN);
    }

    cudaMemcpyAsync(d_out, feat, (size_t)ND*sizeof(float), cudaMemcpyDeviceToDevice, 0);
    if (out_size >= ND + TT*DD) {
        cudaMemcpyAsync((float*)d_out + ND, e_emb, TT*DD*sizeof(float),
                        cudaMemcpyDeviceToDevice, 0);
    }
}

// round 8
// speedup vs baseline: 1.4038x; 1.0838x over previous
#include <cuda_runtime.h>
#include <cuda_bf16.h>
#include <cstdint>
#include <math.h>

#define NN 100000
#define DD 128
#define EE 250000
#define TT 3
#define ND (NN*DD)
#define ND4 (ND/4)

// -------- scratch --------
__device__ float g_feat[ND];
__device__ float g_t1[ND];
__device__ float g_t2[ND];
__device__ float g_key[3*ND];
__device__ float g_ska[3*ND];
__device__ float g_v[3*ND];
__device__ int   g_cnt[TT*NN];
__device__ float g_inv[TT*NN];
__device__ float g_gscale[NN];
__device__ float g_colsum[DD];
__device__ float g_colsq[DD];
__device__ float g_wqa[DD*DD];
__device__ float g_wka[DD*DD];

// -------- small kernels (float4-vectorized) --------

__global__ void gather_feat_k(const float* __restrict__ n_emb, const int* __restrict__ ind,
                              float* __restrict__ feat) {
    int idx = blockIdx.x * blockDim.x + threadIdx.x;
    if (idx >= ND4) return;
    int n = idx >> 5;
    reinterpret_cast<float4*>(feat)[idx] =
        reinterpret_cast<const float4*>(n_emb)[(long)ind[n] * 32 + (idx & 31)];
}

__global__ void count_k(const int* __restrict__ dst, int* __restrict__ cnt) {
    int e = blockIdx.x * blockDim.x + threadIdx.x;
    if (e >= TT*EE) return;
    int t = e / EE;
    atomicAdd(&cnt[t * NN + dst[e]], 1);
}

__global__ void prep_k(const int* __restrict__ cnt, float* __restrict__ inv,
                       float* __restrict__ gscale) {
    int n = blockIdx.x * blockDim.x + threadIdx.x;
    if (n >= NN) return;
    int c0 = cnt[n], c1 = cnt[NN + n], c2 = cnt[2*NN + n];
    inv[n]        = 1.f / (float)max(c0, 1);
    inv[NN + n]   = 1.f / (float)max(c1, 1);
    inv[2*NN + n] = 1.f / (float)max(c2, 1);
    gscale[n] = (float)((c0 > 0) + (c1 > 0) + (c2 > 0));
}

__global__ void init_acc_k(const float* __restrict__ feat, const float* __restrict__ gscale,
                           float* __restrict__ acc) {
    int idx = blockIdx.x * blockDim.x + threadIdx.x;
    if (idx >= ND4) return;
    float s = gscale[idx >> 5];
    float4 f = reinterpret_cast<const float4*>(feat)[idx];
    reinterpret_cast<float4*>(acc)[idx] = make_float4(f.x*s, f.y*s, f.z*s, f.w*s);
}

__device__ __forceinline__ void red_add_v4(float* p, float4 v) {
    asm volatile("red.global.add.v4.f32 [%0], {%1,%2,%3,%4};"
                 :: "l"(p), "f"(v.x), "f"(v.y), "f"(v.z), "f"(v.w) : "memory");
}

__global__ void gcn_edge_k(const float* __restrict__ feat, const float* __restrict__ emb,
                           const int* __restrict__ src, const int* __restrict__ dst,
                           const float* __restrict__ inv, float* __restrict__ acc) {
    int gw = (blockIdx.x * blockDim.x + threadIdx.x) >> 5;
    int lane = threadIdx.x & 31;
    if (gw >= TT*EE) return;
    int t = gw / EE;
    int s = src[gw], d = dst[gw];
    float w = inv[t * NN + d];
    float4 f = reinterpret_cast<const float4*>(feat + (long)s * DD)[lane];
    float4 e = reinterpret_cast<const float4*>(emb + t * DD)[lane];
    float4 v = make_float4(-f.x*e.x*w, -f.y*e.y*w, -f.z*e.z*w, -f.w*e.w*w);
    red_add_v4(acc + (long)d * DD + lane*4, v);
}

__global__ void attn_edge_k(const float* __restrict__ feat, const float* __restrict__ emb,
                            const int* __restrict__ src, const int* __restrict__ dst,
                            const float* __restrict__ inv, float* __restrict__ key) {
    int gw = (blockIdx.x * blockDim.x + threadIdx.x) >> 5;
    int lane = threadIdx.x & 31;
    if (gw >= TT*EE) return;
    int t = gw / EE;
    int s = src[gw], d = dst[gw];
    float w = inv[t * NN + d];
    float4 f = reinterpret_cast<const float4*>(feat + (long)s * DD)[lane];
    float4 e = reinterpret_cast<const float4*>(emb + t * DD)[lane];
    float4 v = make_float4(f.x*e.x*w, f.y*e.y*w, f.z*e.z*w, f.w*e.w*w);
    red_add_v4(key + (long)t * ND + (long)d * DD + lane*4, v);
}

// -------- tf32 tensor-core GEMM with cp.async double buffering --------
// C[M,128] = A[M,128] @ B[128,128]. EPI==1: C += acc + bias[col].
// f32 bits fed directly to tf32 MMA (HW mantissa truncation).

#define GSTAGE_A (128*36)
#define GSTAGE_B (32*136)
#define GSTAGE   (GSTAGE_A + GSTAGE_B)
#define GEMM_SMEM_BYTES (2*GSTAGE*4)

__device__ __forceinline__ void cp_async16(uint32_t saddr, const void* gptr, bool pred) {
    int sz = pred ? 16 : 0;
    asm volatile("cp.async.ca.shared.global [%0], [%1], 16, %2;"
                 :: "r"(saddr), "l"(gptr), "r"(sz));
}

__device__ __forceinline__ void mma_tf32(float* c, const uint32_t* a, const uint32_t* b) {
    asm volatile("mma.sync.aligned.m16n8k8.row.col.f32.tf32.tf32.f32 "
                 "{%0,%1,%2,%3}, {%4,%5,%6,%7}, {%8,%9}, {%0,%1,%2,%3};"
                 : "+f"(c[0]), "+f"(c[1]), "+f"(c[2]), "+f"(c[3])
                 : "r"(a[0]), "r"(a[1]), "r"(a[2]), "r"(a[3]), "r"(b[0]), "r"(b[1]));
}

template<int EPI>
__global__ __launch_bounds__(256) void gemm_tc(const float* __restrict__ A,
                                               const float* __restrict__ B,
                                               float* __restrict__ C,
                                               const float* __restrict__ bias, int M) {
    extern __shared__ float smf[];
    int tid = threadIdx.x;
    int lane = tid & 31, wid = tid >> 5;
    int wm = wid & 3, wn = wid >> 2;
    int g = lane >> 2, q = lane & 3;
    long m0 = (long)blockIdx.x * 128;

    float acc[2][8][4];
    #pragma unroll
    for (int mt = 0; mt < 2; mt++)
        #pragma unroll
        for (int nt = 0; nt < 8; nt++)
            #pragma unroll
            for (int i = 0; i < 4; i++) acc[mt][nt][i] = 0.f;

    // per-thread staging coordinates (constant across chunks)
    int ar[4], ac_[4], br[4], bc[4];
    #pragma unroll
    for (int i = 0; i < 4; i++) {
        int idx = (tid + 256 * i) * 4;
        ar[i] = idx >> 5; ac_[i] = idx & 31;        // A: 128x32
        br[i] = idx >> 7; bc[i] = idx & 127;        // B: 32x128
    }

    auto prefetch = [&](int kc, int s) {
        float* As = smf + s * GSTAGE;
        float* Bs = As + GSTAGE_A;
        #pragma unroll
        for (int i = 0; i < 4; i++) {
            long row = m0 + ar[i];
            uint32_t sa = (uint32_t)__cvta_generic_to_shared(&As[ar[i]*36 + ac_[i]]);
            cp_async16(sa, A + row * 128 + kc * 32 + ac_[i], row < M);
        }
        #pragma unroll
        for (int i = 0; i < 4; i++) {
            uint32_t sb = (uint32_t)__cvta_generic_to_shared(&Bs[br[i]*136 + bc[i]]);
            cp_async16(sb, B + (kc * 32 + br[i]) * 128 + bc[i], true);
        }
        asm volatile("cp.async.commit_group;");
    };

    prefetch(0, 0);

    for (int kc = 0; kc < 4; kc++) {
        if (kc < 3) {
            prefetch(kc + 1, (kc + 1) & 1);
            asm volatile("cp.async.wait_group 1;");
        } else {
            asm volatile("cp.async.wait_group 0;");
        }
        __syncthreads();

        const uint32_t* As = reinterpret_cast<const uint32_t*>(smf + (kc & 1) * GSTAGE);
        const uint32_t* Bs = As + GSTAGE_A;

        #pragma unroll
        for (int ks = 0; ks < 4; ks++) {
            int kc8 = ks * 8;
            uint32_t a[2][4], b[8][2];
            #pragma unroll
            for (int mt = 0; mt < 2; mt++) {
                int row = wm * 32 + mt * 16 + g;
                a[mt][0] = As[row*36 + kc8 + q];
                a[mt][1] = As[(row+8)*36 + kc8 + q];
                a[mt][2] = As[row*36 + kc8 + q + 4];
                a[mt][3] = As[(row+8)*36 + kc8 + q + 4];
            }
            #pragma unroll
            for (int nt = 0; nt < 8; nt++) {
                int col = wn * 64 + nt * 8 + g;
                b[nt][0] = Bs[(kc8 + q)*136 + col];
                b[nt][1] = Bs[(kc8 + q + 4)*136 + col];
            }
            #pragma unroll
            for (int mt = 0; mt < 2; mt++)
                #pragma unroll
                for (int nt = 0; nt < 8; nt++)
                    mma_tf32(acc[mt][nt], a[mt], b[nt]);
        }
        __syncthreads();
    }

    #pragma unroll
    for (int mt = 0; mt < 2; mt++) {
        #pragma unroll
        for (int h = 0; h < 2; h++) {
            long row = m0 + wm * 32 + mt * 16 + g + h * 8;
            if (row >= M) continue;
            #pragma unroll
            for (int nt = 0; nt < 8; nt++) {
                int col = wn * 64 + nt * 8 + q * 2;
                float2* cp = reinterpret_cast<float2*>(&C[row * 128 + col]);
                float v0 = acc[mt][nt][h * 2], v1 = acc[mt][nt][h * 2 + 1];
                if (EPI == 0) {
                    *cp = make_float2(v0, v1);
                } else {
                    float2 prev = *cp;
                    *cp = make_float2(prev.x + v0 + bias[col], prev.y + v1 + bias[col + 1]);
                }
            }
        }
    }
}

// -------- BN / softmax kernels --------

__global__ void bn_stats_k(const float* __restrict__ h, float* __restrict__ colsum,
                           float* __restrict__ colsq) {
    __shared__ float ssum[128], ssq[128];
    int tid = threadIdx.x;
    if (tid < 128) { ssum[tid] = 0.f; ssq[tid] = 0.f; }
    __syncthreads();
    int c4 = tid & 31;
    int rstep = gridDim.x * 8;
    float4 s = make_float4(0,0,0,0), s2 = make_float4(0,0,0,0);
    for (int r = blockIdx.x * 8 + (tid >> 5); r < NN; r += rstep) {
        float4 x = reinterpret_cast<const float4*>(h)[(long)r * 32 + c4];
        s.x += x.x; s.y += x.y; s.z += x.z; s.w += x.w;
        s2.x += x.x*x.x; s2.y += x.y*x.y; s2.z += x.z*x.z; s2.w += x.w*x.w;
    }
    atomicAdd(&ssum[c4*4+0], s.x);  atomicAdd(&ssq[c4*4+0], s2.x);
    atomicAdd(&ssum[c4*4+1], s.y);  atomicAdd(&ssq[c4*4+1], s2.y);
    atomicAdd(&ssum[c4*4+2], s.z);  atomicAdd(&ssq[c4*4+2], s2.z);
    atomicAdd(&ssum[c4*4+3], s.w);  atomicAdd(&ssq[c4*4+3], s2.w);
    __syncthreads();
    if (tid < 128) {
        atomicAdd(&colsum[tid], ssum[tid]);
        atomicAdd(&colsq[tid], ssq[tid]);
    }
}

__global__ void bn_apply_relu_k(float* __restrict__ h, const float* __restrict__ gamma,
                                const float* __restrict__ beta,
                                const float* __restrict__ colsum,
                                const float* __restrict__ colsq) {
    __shared__ float sm_mean[128], sm_scale[128], sm_beta[128];
    int tid = threadIdx.x;
    if (tid < 128) {
        const float invN = 1.f / (float)NN;
        float mean = colsum[tid] * invN;
        float var  = colsq[tid] * invN - mean * mean;
        sm_mean[tid] = mean;
        sm_scale[tid] = rsqrtf(var + 1e-5f) * gamma[tid];
        sm_beta[tid] = beta[tid];
    }
    __syncthreads();
    int idx = blockIdx.x * blockDim.x + tid;
    if (idx >= ND4) return;
    int c = (idx & 31) * 4;
    float4 x = reinterpret_cast<float4*>(h)[idx];
    float4 o;
    o.x = fmaxf((x.x - sm_mean[c+0]) * sm_scale[c+0] + sm_beta[c+0], 0.f);
    o.y = fmaxf((x.y - sm_mean[c+1]) * sm_scale[c+1] + sm_beta[c+1], 0.f);
    o.z = fmaxf((x.z - sm_mean[c+2]) * sm_scale[c+2] + sm_beta[c+2], 0.f);
    o.w = fmaxf((x.w - sm_mean[c+3]) * sm_scale[c+3] + sm_beta[c+3], 0.f);
    reinterpret_cast<float4*>(h)[idx] = o;
}

__global__ void attn_combine_k(const float* __restrict__ qa, const float* __restrict__ ska,
                               const float* __restrict__ vv, float* __restrict__ o) {
    int idx = blockIdx.x * blockDim.x + threadIdx.x;
    if (idx >= ND4) return;
    float4 q  = reinterpret_cast<const float4*>(qa)[idx];
    float4 s0 = reinterpret_cast<const float4*>(ska)[idx];
    float4 s1 = reinterpret_cast<const float4*>(ska)[idx + ND4];
    float4 s2 = reinterpret_cast<const float4*>(ska)[idx + 2*ND4];
    float4 v0 = reinterpret_cast<const float4*>(vv)[idx];
    float4 v1 = reinterpret_cast<const float4*>(vv)[idx + ND4];
    float4 v2 = reinterpret_cast<const float4*>(vv)[idx + 2*ND4];
    float4 r;
    const float* pq = &q.x; const float* p0 = &s0.x; const float* p1 = &s1.x;
    const float* p2 = &s2.x; const float* w0 = &v0.x; const float* w1 = &v1.x;
    const float* w2 = &v2.x; float* pr = &r.x;
    #pragma unroll
    for (int j = 0; j < 4; j++) {
        float l0 = pq[j] - p0[j], l1 = pq[j] - p1[j], l2 = pq[j] - p2[j];
        float m = fmaxf(l0, fmaxf(l1, l2));
        float e0 = __expf(l0 - m), e1 = __expf(l1 - m), e2 = __expf(l2 - m);
        pr[j] = (e0 * w0[j] + e1 * w1[j] + e2 * w2[j]) / (e0 + e1 + e2);
    }
    reinterpret_cast<float4*>(o)[idx] = r;
}

// -------- host --------

extern "C" void kernel_launch(void* const* d_in, const int* in_sizes, int n_in,
                              void* d_out, int out_size) {
    const float* e_emb = (const float*)d_in[1];
    const int* node_ind = (const int*)d_in[26];
    const int* edge_src = (const int*)d_in[27];
    const int* edge_dst = (const int*)d_in[28];

    float *feat, *t1, *t2, *key, *ska, *vv, *inv, *gscale, *colsum, *colsq, *wqa, *wka;
    int* cnt;
    cudaGetSymbolAddress((void**)&feat, g_feat);
    cudaGetSymbolAddress((void**)&t1, g_t1);
    cudaGetSymbolAddress((void**)&t2, g_t2);
    cudaGetSymbolAddress((void**)&key, g_key);
    cudaGetSymbolAddress((void**)&ska, g_ska);
    cudaGetSymbolAddress((void**)&vv, g_v);
    cudaGetSymbolAddress((void**)&cnt, g_cnt);
    cudaGetSymbolAddress((void**)&inv, g_inv);
    cudaGetSymbolAddress((void**)&gscale, g_gscale);
    cudaGetSymbolAddress((void**)&colsum, g_colsum);
    cudaGetSymbolAddress((void**)&colsq, g_colsq);
    cudaGetSymbolAddress((void**)&wqa, g_wqa);
    cudaGetSymbolAddress((void**)&wka, g_wka);

    cudaFuncSetAttribute(gemm_tc<0>, cudaFuncAttributeMaxDynamicSharedMemorySize,
                         GEMM_SMEM_BYTES);
    cudaFuncSetAttribute(gemm_tc<1>, cudaFuncAttributeMaxDynamicSharedMemorySize,
                         GEMM_SMEM_BYTES);

    const int TPB = 256;
    const int ND4_BLK = (ND4 + TPB - 1) / TPB;
    const int EDGE_BLK = (TT*EE*32 + TPB - 1) / TPB;
    const int G1 = (NN + 127) / 128;
    const int G3 = (TT*NN + 127) / 128;

    cudaMemsetAsync(cnt, 0, TT*NN*sizeof(int), 0);
    count_k<<<(TT*EE + TPB - 1)/TPB, TPB>>>(edge_dst, cnt);
    prep_k<<<(NN + TPB - 1)/TPB, TPB>>>(cnt, inv, gscale);
    gather_feat_k<<<ND4_BLK, TPB>>>((const float*)d_in[0], node_ind, feat);

    const float* gcn_w1[2]    = {(const float*)d_in[2],  (const float*)d_in[14]};
    const float* gcn_gamma[2] = {(const float*)d_in[3],  (const float*)d_in[15]};
    const float* gcn_beta[2]  = {(const float*)d_in[4],  (const float*)d_in[16]};
    const float* gcn_w2[2]    = {(const float*)d_in[5],  (const float*)d_in[17]};
    const float* gcn_b2[2]    = {(const float*)d_in[6],  (const float*)d_in[18]};
    const float* at_wq[2]     = {(const float*)d_in[7],  (const float*)d_in[19]};
    const float* at_wk[2]     = {(const float*)d_in[8],  (const float*)d_in[20]};
    const float* at_wv[2]     = {(const float*)d_in[9],  (const float*)d_in[21]};
    const float* at_wa[2]     = {(const float*)d_in[10], (const float*)d_in[22]};
    const float* at_wp[2]     = {(const float*)d_in[12], (const float*)d_in[24]};
    const float* at_bp[2]     = {(const float*)d_in[13], (const float*)d_in[25]};

    for (int L = 0; L < 2; L++) {
        // ---- GCN layer ----
        init_acc_k<<<ND4_BLK, TPB>>>(feat, gscale, t1);
        gcn_edge_k<<<EDGE_BLK, TPB>>>(feat, e_emb, edge_src, edge_dst, inv, t1);
        gemm_tc<0><<<G1, 256, GEMM_SMEM_BYTES>>>(t1, gcn_w1[L], t2, nullptr, NN);
        cudaMemsetAsync(colsum, 0, DD*sizeof(float), 0);
        cudaMemsetAsync(colsq, 0, DD*sizeof(float), 0);
        bn_stats_k<<<1024, 256>>>(t2, colsum, colsq);
        bn_apply_relu_k<<<ND4_BLK, TPB>>>(t2, gcn_gamma[L], gcn_beta[L], colsum, colsq);
        gemm_tc<1><<<G1, 256, GEMM_SMEM_BYTES>>>(t2, gcn_w2[L], feat, gcn_b2[L], NN);

        // ---- Attention layer ----
        gemm_tc<0><<<1, 256, GEMM_SMEM_BYTES>>>(at_wq[L], at_wa[L], wqa, nullptr, 128);
        gemm_tc<0><<<1, 256, GEMM_SMEM_BYTES>>>(at_wk[L], at_wa[L], wka, nullptr, 128);
        cudaMemsetAsync(key, 0, (size_t)3*ND*sizeof(float), 0);
        attn_edge_k<<<EDGE_BLK, TPB>>>(feat, e_emb, edge_src, edge_dst, inv, key);
        gemm_tc<0><<<G1, 256, GEMM_SMEM_BYTES>>>(feat, wqa, t1, nullptr, NN);
        gemm_tc<0><<<G3, 256, GEMM_SMEM_BYTES>>>(key, wka, ska, nullptr, TT*NN);
        gemm_tc<0><<<G3, 256, GEMM_SMEM_BYTES>>>(key, at_wv[L], vv, nullptr, TT*NN);
        attn_combine_k<<<ND4_BLK, TPB>>>(t1, ska, vv, t2);
        gemm_tc<1><<<G1, 256, GEMM_SMEM_BYTES>>>(t2, at_wp[L], feat, at_bp[L], NN);
    }

    cudaMemcpyAsync(d_out, feat, (size_t)ND*sizeof(float), cudaMemcpyDeviceToDevice, 0);
    if (out_size >= ND + TT*DD) {
        cudaMemcpyAsync((float*)d_out + ND, e_emb, TT*DD*sizeof(float),
                        cudaMemcpyDeviceToDevice, 0);
    }
}